// round 12
// baseline (speedup 1.0000x reference)
#include <cuda_runtime.h>
#include <cuda_fp16.h>
#include <cstdint>

// R12: warp-local MLP. L1 f16 k8 MMA; L2/L3 e4m3 m16n8k32 (f32 accum, bias-init).
// Feature permutation sigma baked into W2/W3 B-frag staging so the f16->fp8
// A-frag repack is lane-local: 2 cvt + 1 lop3 per reg (no shfl/selp).

#define SP    262144
#define TB    256
#define GRID  512
#define TILES 8          // 512*8*128 = 524288 voxels

// smem offsets
#define O_W2T8 0         // 1024 * 16 B  (c<4, tp<8, lane)
#define O_W3T8 16384     // 512 * 16    (c<4, tp<4, lane)
#define O_W1T  24576     // 256 * 8     (f16 k8 frags)
#define O_B1H  26624     // 64 * 4 (f16x2)
#define O_B2F  26880     // 64 * 8 (f32 pairs)
#define O_B3F  27392     // 32 * 8
#define O_W4H  27648     // 96 * 4 (f16x2, pre-scaled by 0.1)
#define O_B4   28032     // 3 f32 (pre-scaled), +pad
#define O_LZ   28048     // 128 * 3 f32 lorentz stash
#define SMEM_BYTES 29584

#define MMAH8(c0, c1, a0, a1, b0) asm volatile( \
    "mma.sync.aligned.m16n8k8.row.col.f16.f16.f16.f16 " \
    "{%0,%1}, {%2,%3}, {%4}, {%0,%1};" \
    : "+r"(c0), "+r"(c1) : "r"(a0), "r"(a1), "r"(b0))

#define MMAQ(c, a0, a1, a2, a3, b0, b1) asm volatile( \
    "mma.sync.aligned.m16n8k32.row.col.f32.e4m3.e4m3.f32 " \
    "{%0,%1,%2,%3}, {%4,%5,%6,%7}, {%8,%9}, {%0,%1,%2,%3};" \
    : "+f"((c)[0]), "+f"((c)[1]), "+f"((c)[2]), "+f"((c)[3]) \
    : "r"(a0), "r"(a1), "r"(a2), "r"(a3), "r"(b0), "r"(b1))

__device__ __forceinline__ uint32_t smem_u32(const void* p) {
    uint32_t a;
    asm("{ .reg .u64 t; cvta.to.shared.u64 t, %1; cvt.u32.u64 %0, t; }" : "=r"(a) : "l"(p));
    return a;
}
__device__ __forceinline__ uint32_t lds32(uint32_t a) {
    uint32_t v; asm volatile("ld.shared.b32 %0, [%1];" : "=r"(v) : "r"(a)); return v;
}
__device__ __forceinline__ uint2 lds64(uint32_t a) {
    uint2 v; asm volatile("ld.shared.v2.b32 {%0,%1}, [%2];" : "=r"(v.x), "=r"(v.y) : "r"(a)); return v;
}
__device__ __forceinline__ uint4 lds128(uint32_t a) {
    uint4 v;
    asm volatile("ld.shared.v4.b32 {%0,%1,%2,%3}, [%4];"
                 : "=r"(v.x), "=r"(v.y), "=r"(v.z), "=r"(v.w) : "r"(a));
    return v;
}
__device__ __forceinline__ uint32_t packh(float a, float b) {
    __half2 h = __floats2half2_rn(a, b);
    return *(uint32_t*)&h;
}
// e4m3 pair converters (low byte = first arg) — byte order proven in R10
__device__ __forceinline__ uint32_t e4m3x2_f32(float a, float b) {
    uint16_t d;
    asm("cvt.rn.satfinite.e4m3x2.f32 %0, %1, %2;" : "=h"(d) : "f"(b), "f"(a));
    return (uint32_t)d;
}
__device__ __forceinline__ uint32_t e4m3x2_h2(uint32_t h2) {
    uint16_t d;
    asm("cvt.rn.satfinite.e4m3x2.f16x2 %0, %1;" : "=h"(d) : "r"(h2));
    return (uint32_t)d;
}
// gelu(tanh) on packed f16x2
__device__ __forceinline__ uint32_t gel(uint32_t xu) {
    __half2 x = *(__half2*)&xu;
    const __half2 c0 = __float2half2_rn(0.7978845608f);
    const __half2 c1 = __float2half2_rn(0.03567740814f);
    __half2 u = __hmul2(x, x);
    __half2 z = __hmul2(x, __hfma2(u, c1, c0));
    uint32_t zi = *(uint32_t*)&z, ti;
    asm("tanh.approx.f16x2 %0, %1;" : "=r"(ti) : "r"(zi));
    __half2 t = *(__half2*)&ti;
    __half2 hh = __hmul2(x, __float2half2_rn(0.5f));
    __half2 g = __hfma2(hh, t, hh);
    return *(uint32_t*)&g;
}
__device__ __forceinline__ uint32_t gb(uint32_t cu, uint32_t bu) {
    __half2 x = __hadd2(*(__half2*)&cu, *(__half2*)&bu);
    return gel(*(uint32_t*)&x);
}
// sigma: k-slot (c, h, i, q) -> feature id
__device__ __forceinline__ int sigf(int c, int h, int i, int q) {
    return 8 * (4 * c + 2 * h + (i >> 1)) + 2 * q + (i & 1);
}

__global__ void __launch_bounds__(TB, 3)
mhd_q8b(const float* __restrict__ flow, const float* __restrict__ Bf,
        const float* __restrict__ W1, const float* __restrict__ b1,
        const float* __restrict__ W2, const float* __restrict__ b2,
        const float* __restrict__ W3, const float* __restrict__ b3,
        const float* __restrict__ W4, const float* __restrict__ b4,
        float* __restrict__ out)
{
    extern __shared__ char smc[];
    const int tid  = threadIdx.x;
    const int wid  = tid >> 5;
    const int lane = tid & 31;
    const int q    = lane & 3;
    const int rsub = lane >> 2;
    const uint32_t smb = smem_u32(smc);

    // ---------------- stage weights ----------------
    // W2 fp8 B-frags with sigma'd k rows
    for (int e = tid; e < 1024; e += TB) {
        int l = e & 31, tp = (e >> 5) & 7, c = e >> 8;
        int ql = l & 3;
        int n0 = 2 * tp * 8 + (l >> 2), n1 = n0 + 8;
        uint4 v;
        v.x = e4m3x2_f32(W2[sigf(c,0,0,ql)*128+n0], W2[sigf(c,0,1,ql)*128+n0])
            | (e4m3x2_f32(W2[sigf(c,0,2,ql)*128+n0], W2[sigf(c,0,3,ql)*128+n0]) << 16);
        v.y = e4m3x2_f32(W2[sigf(c,1,0,ql)*128+n0], W2[sigf(c,1,1,ql)*128+n0])
            | (e4m3x2_f32(W2[sigf(c,1,2,ql)*128+n0], W2[sigf(c,1,3,ql)*128+n0]) << 16);
        v.z = e4m3x2_f32(W2[sigf(c,0,0,ql)*128+n1], W2[sigf(c,0,1,ql)*128+n1])
            | (e4m3x2_f32(W2[sigf(c,0,2,ql)*128+n1], W2[sigf(c,0,3,ql)*128+n1]) << 16);
        v.w = e4m3x2_f32(W2[sigf(c,1,0,ql)*128+n1], W2[sigf(c,1,1,ql)*128+n1])
            | (e4m3x2_f32(W2[sigf(c,1,2,ql)*128+n1], W2[sigf(c,1,3,ql)*128+n1]) << 16);
        *(uint4*)(smc + O_W2T8 + e * 16) = v;
    }
    // W3 fp8 B-frags with sigma'd k rows
    for (int e = tid; e < 512; e += TB) {
        int l = e & 31, tp = (e >> 5) & 3, c = e >> 7;
        int ql = l & 3;
        int n0 = 2 * tp * 8 + (l >> 2), n1 = n0 + 8;
        uint4 v;
        v.x = e4m3x2_f32(W3[sigf(c,0,0,ql)*64+n0], W3[sigf(c,0,1,ql)*64+n0])
            | (e4m3x2_f32(W3[sigf(c,0,2,ql)*64+n0], W3[sigf(c,0,3,ql)*64+n0]) << 16);
        v.y = e4m3x2_f32(W3[sigf(c,1,0,ql)*64+n0], W3[sigf(c,1,1,ql)*64+n0])
            | (e4m3x2_f32(W3[sigf(c,1,2,ql)*64+n0], W3[sigf(c,1,3,ql)*64+n0]) << 16);
        v.z = e4m3x2_f32(W3[sigf(c,0,0,ql)*64+n1], W3[sigf(c,0,1,ql)*64+n1])
            | (e4m3x2_f32(W3[sigf(c,0,2,ql)*64+n1], W3[sigf(c,0,3,ql)*64+n1]) << 16);
        v.w = e4m3x2_f32(W3[sigf(c,1,0,ql)*64+n1], W3[sigf(c,1,1,ql)*64+n1])
            | (e4m3x2_f32(W3[sigf(c,1,2,ql)*64+n1], W3[sigf(c,1,3,ql)*64+n1]) << 16);
        *(uint4*)(smc + O_W3T8 + e * 16) = v;
    }
    // W1 f16 k8 frags (k>=6 zero)
    for (int e = tid; e < 256; e += TB) {
        int l = e & 31, tp = e >> 5;
        int n0 = 2 * tp * 8 + (l >> 2), n1 = n0 + 8;
        int k0 = (l & 3) * 2;
        float a0 = (k0 < 6) ? W1[k0 * 128 + n0] : 0.f;
        float a1 = (k0 + 1 < 6) ? W1[(k0 + 1) * 128 + n0] : 0.f;
        float a2 = (k0 < 6) ? W1[k0 * 128 + n1] : 0.f;
        float a3 = (k0 + 1 < 6) ? W1[(k0 + 1) * 128 + n1] : 0.f;
        uint2 v; v.x = packh(a0, a1); v.y = packh(a2, a3);
        *(uint2*)(smc + O_W1T + e * 8) = v;
    }
    for (int i = tid; i < 64; i += TB)
        *(uint32_t*)(smc + O_B1H + i * 4) = packh(b1[(i >> 2) * 8 + (i & 3) * 2],
                                                  b1[(i >> 2) * 8 + (i & 3) * 2 + 1]);
    for (int i = tid; i < 64; i += TB) {
        int n = (i >> 2) * 8 + (i & 3) * 2;
        *(float2*)(smc + O_B2F + i * 8) = make_float2(b2[n], b2[n + 1]);
    }
    for (int i = tid; i < 32; i += TB) {
        int n = (i >> 2) * 8 + (i & 3) * 2;
        *(float2*)(smc + O_B3F + i * 8) = make_float2(b3[n], b3[n + 1]);
    }
    for (int i = tid; i < 96; i += TB) {   // 0.1*W4
        int c = i >> 5, p = i & 31;
        *(uint32_t*)(smc + O_W4H + i * 4) = packh(0.1f * W4[2 * p * 3 + c],
                                                  0.1f * W4[(2 * p + 1) * 3 + c]);
    }
    if (tid < 3) ((float*)(smc + O_B4))[tid] = 0.1f * b4[tid];
    __syncthreads();   // only block barrier

    for (int it = 0; it < TILES; it++) {
        const int tile = it * GRID + blockIdx.x;
        const int vbase = tile * 128 + wid * 16;
        const int b  = vbase >> 18;
        const int sb = vbase & (SP - 1);
        const float* Fb = flow + b * 3 * SP;
        const float* Bx = Bf + b * 3 * SP;
        const float* By = Bx + SP;
        const float* Bz = Bx + 2 * SP;

        // ---------------- P0: features + lorentz -> smem stash ----------------
        const int s0 = sb + rsub, s1 = s0 + 8;
        uint32_t fa0, fa1;
        {
            float l0, h0, l1, h1;
            if (q == 0)      { l0 = Fb[s0]; h0 = Fb[SP + s0]; l1 = Fb[s1]; h1 = Fb[SP + s1]; }
            else if (q == 1) { l0 = Fb[2 * SP + s0]; h0 = Bx[s0]; l1 = Fb[2 * SP + s1]; h1 = Bx[s1]; }
            else if (q == 2) { l0 = By[s0]; h0 = Bz[s0]; l1 = By[s1]; h1 = Bz[s1]; }
            else             { l0 = h0 = l1 = h1 = 0.f; }
            fa0 = packh(l0, h0);
            fa1 = packh(l1, h1);
        }
        __syncwarp();
        if (lane < 16) {
            const int sm = sb + lane;
            const int h = sm >> 12, w = (sm >> 6) & 63, d = sm & 63;
            const int H = h << 12, Wo = w << 6;
            const int hp = ((h + 1) & 63) << 12, hm = ((h - 1) & 63) << 12;
            const int wp = ((w + 1) & 63) << 6,  wm2 = ((w - 1) & 63) << 6;
            const int dp = (d + 1) & 63, dm = (d - 1) & 63;
            const float bx = Bx[H + Wo + d], by = By[H + Wo + d], bz = Bz[H + Wo + d];
            const float Jx = 0.5f * ((Bz[H + wp + d] - Bz[H + wm2 + d]) - (By[H + Wo + dp] - By[H + Wo + dm]));
            const float Jy = 0.5f * ((Bx[H + Wo + dp] - Bx[H + Wo + dm]) - (Bz[hp + Wo + d] - Bz[hm + Wo + d]));
            const float Jz = 0.5f * ((By[hp + Wo + d] - By[hm + Wo + d]) - (Bx[H + wp + d] - Bx[H + wm2 + d]));
            float* lz = (float*)(smc + O_LZ) + (wid * 16 + lane) * 3;
            lz[0] = (Jy * bz - Jz * by) * 2500.0f;
            lz[1] = (Jz * bx - Jx * bz) * 2500.0f;
            lz[2] = (Jx * by - Jy * bx) * 2500.0f;
        }

        // ---------------- L1 (f16 k8): 6 -> 128; pack to fp8 A-frags ----------
        uint32_t aA[4][2], aB[4][2];   // x1 as fp8 A-frags (rows r / r+8)
        {
            uint32_t c1[16][2];
            #pragma unroll
            for (int t = 0; t < 16; t++) { c1[t][0] = 0u; c1[t][1] = 0u; }
            #pragma unroll
            for (int tp = 0; tp < 8; tp++) {
                uint2 B1f = lds64(smb + O_W1T + (uint32_t)(tp * 32 + lane) * 8);
                MMAH8(c1[2 * tp][0], c1[2 * tp][1], fa0, fa1, B1f.x);
                MMAH8(c1[2 * tp + 1][0], c1[2 * tp + 1][1], fa0, fa1, B1f.y);
            }
            #pragma unroll
            for (int cc = 0; cc < 4; cc++)
                #pragma unroll
                for (int h = 0; h < 2; h++) {
                    const int t0 = 4 * cc + 2 * h, t1 = t0 + 1;
                    uint32_t b0 = lds32(smb + O_B1H + (uint32_t)(t0 * 4 + q) * 4);
                    uint32_t b1u = lds32(smb + O_B1H + (uint32_t)(t1 * 4 + q) * 4);
                    aA[cc][h] = e4m3x2_h2(gb(c1[t0][0], b0)) | (e4m3x2_h2(gb(c1[t1][0], b1u)) << 16);
                    aB[cc][h] = e4m3x2_h2(gb(c1[t0][1], b0)) | (e4m3x2_h2(gb(c1[t1][1], b1u)) << 16);
                }
        }

        // ---------------- L2 (fp8 k32): 128 -> 128, t-halved, bias-init -------
        uint32_t vA[4][2], vB[4][2];   // x2 fp8 A-frags
        #pragma unroll
        for (int th = 0; th < 2; th++) {
            float c2[8][4];
            #pragma unroll
            for (int tl = 0; tl < 8; tl++) {
                uint2 bf = lds64(smb + O_B2F + (uint32_t)((8 * th + tl) * 4 + q) * 8);
                c2[tl][0] = __uint_as_float(bf.x);
                c2[tl][1] = __uint_as_float(bf.y);
                c2[tl][2] = __uint_as_float(bf.x);
                c2[tl][3] = __uint_as_float(bf.y);
            }
            #pragma unroll
            for (int cc = 0; cc < 4; cc++) {
                #pragma unroll
                for (int tpl = 0; tpl < 4; tpl++) {
                    const int tp = 4 * th + tpl;
                    uint4 Bq = lds128(smb + O_W2T8 + (uint32_t)((cc * 8 + tp) * 32 + lane) * 16);
                    MMAQ(c2[2 * tpl], aA[cc][0], aB[cc][0], aA[cc][1], aB[cc][1], Bq.x, Bq.y);
                    MMAQ(c2[2 * tpl + 1], aA[cc][0], aB[cc][0], aA[cc][1], aB[cc][1], Bq.z, Bq.w);
                }
            }
            #pragma unroll
            for (int pp = 0; pp < 4; pp++) {
                const int t0 = 2 * pp, t1 = t0 + 1;
                const int cc = 2 * th + (pp >> 1), h = pp & 1;
                vA[cc][h] = e4m3x2_h2(gel(packh(c2[t0][0], c2[t0][1])))
                          | (e4m3x2_h2(gel(packh(c2[t1][0], c2[t1][1]))) << 16);
                vB[cc][h] = e4m3x2_h2(gel(packh(c2[t0][2], c2[t0][3])))
                          | (e4m3x2_h2(gel(packh(c2[t1][2], c2[t1][3]))) << 16);
            }
        }

        // ---------------- L3 (fp8 k32): 128 -> 64, bias-init ------------------
        uint32_t x3[8][2];             // x3 as f16 pairs for L4
        {
            float c3[8][4];
            #pragma unroll
            for (int tl = 0; tl < 8; tl++) {
                uint2 bf = lds64(smb + O_B3F + (uint32_t)(tl * 4 + q) * 8);
                c3[tl][0] = __uint_as_float(bf.x);
                c3[tl][1] = __uint_as_float(bf.y);
                c3[tl][2] = __uint_as_float(bf.x);
                c3[tl][3] = __uint_as_float(bf.y);
            }
            #pragma unroll
            for (int cc = 0; cc < 4; cc++) {
                #pragma unroll
                for (int tp = 0; tp < 4; tp++) {
                    uint4 Bq = lds128(smb + O_W3T8 + (uint32_t)((cc * 4 + tp) * 32 + lane) * 16);
                    MMAQ(c3[2 * tp], vA[cc][0], vB[cc][0], vA[cc][1], vB[cc][1], Bq.x, Bq.y);
                    MMAQ(c3[2 * tp + 1], vA[cc][0], vB[cc][0], vA[cc][1], vB[cc][1], Bq.z, Bq.w);
                }
            }
            #pragma unroll
            for (int t = 0; t < 8; t++) {
                x3[t][0] = gel(packh(c3[t][0], c3[t][1]));
                x3[t][1] = gel(packh(c3[t][2], c3[t][3]));
            }
        }

        // ---------------- L4: 64 -> 3 (0.1-prescaled) + lorentz + store -------
        __half2 acc[2][3];
        #pragma unroll
        for (int r = 0; r < 2; r++)
            #pragma unroll
            for (int cc = 0; cc < 3; cc++) acc[r][cc] = __float2half2_rn(0.f);
        #pragma unroll
        for (int t = 0; t < 8; t++) {
            #pragma unroll
            for (int cc = 0; cc < 3; cc++) {
                uint32_t wu = lds32(smb + O_W4H + (uint32_t)(cc * 32 + t * 4 + q) * 4);
                __half2 wh = *(__half2*)&wu;
                acc[0][cc] = __hfma2(*(__half2*)&x3[t][0], wh, acc[0][cc]);
                acc[1][cc] = __hfma2(*(__half2*)&x3[t][1], wh, acc[1][cc]);
            }
        }
        float pe[2][3];
        #pragma unroll
        for (int r = 0; r < 2; r++)
            #pragma unroll
            for (int cc = 0; cc < 3; cc++) {
                float2 f = __half22float2(acc[r][cc]);
                float vv = f.x + f.y;
                vv += __shfl_xor_sync(0xffffffffu, vv, 1);
                vv += __shfl_xor_sync(0xffffffffu, vv, 2);
                pe[r][cc] = vv + ((const float*)(smc + O_B4))[cc];
            }
        __syncwarp();
        if (q < 3) {
            const float L0 = ((const float*)(smc + O_LZ))[(wid * 16 + rsub) * 3 + q];
            const float L1 = ((const float*)(smc + O_LZ))[(wid * 16 + rsub + 8) * 3 + q];
            float* ob = out + b * 3 * SP + q * SP;
            ob[s0] = L0 + pe[0][q];
            ob[s1] = L1 + pe[1][q];
        }
    }
}

extern "C" void kernel_launch(void* const* d_in, const int* in_sizes, int n_in,
                              void* d_out, int out_size)
{
    (void)in_sizes; (void)n_in; (void)out_size;
    cudaFuncSetAttribute(mhd_q8b, cudaFuncAttributeMaxDynamicSharedMemorySize, SMEM_BYTES);
    mhd_q8b<<<GRID, TB, SMEM_BYTES>>>(
        (const float*)d_in[0], (const float*)d_in[1], (const float*)d_in[2],
        (const float*)d_in[3], (const float*)d_in[4], (const float*)d_in[5],
        (const float*)d_in[6], (const float*)d_in[7], (const float*)d_in[8],
        (const float*)d_in[9], (float*)d_out);
}

// round 13
// speedup vs baseline: 2.3123x; 2.3123x over previous
#include <cuda_runtime.h>
#include <cuda_fp16.h>
#include <cstdint>

// R13 = R11 (warp-local f16 MLP, 3 CTAs/SM) with a balanced persistent grid:
// GRID=444 (=148*3, all CTAs resident), dynamic strided tile loop over 4096 tiles.

#define SP    262144
#define TB    256
#define GRID  444
#define NTILES 4096      // 524288 voxels / 128

// smem byte offsets
#define O_W2T  0         // 2048 entries * 16 B (sx<8, tp<8, lane)
#define O_W3T  32768     // 1024 * 16 (sx<8, tp<4, lane)
#define O_W1T  49152     // 256 * 8 (f16 k8 frags)
#define O_B1H  51200     // 64 * 4
#define O_B2H  51456     // 64 * 4
#define O_B3H  51712     // 32 * 4
#define O_W4H  51840     // 96 * 4  (c*32 + p)
#define O_B4   52224     // 3 f32 (+pad)
#define O_LZ   52240     // 128 rows * 3 f32 (warp-private lorentz stash)
#define SMEM_BYTES 53776

#define MMAH16(c0, c1, a0, a1, a2, a3, b0, b1) asm volatile( \
    "mma.sync.aligned.m16n8k16.row.col.f16.f16.f16.f16 " \
    "{%0,%1}, {%2,%3,%4,%5}, {%6,%7}, {%0,%1};" \
    : "+r"(c0), "+r"(c1) \
    : "r"(a0), "r"(a1), "r"(a2), "r"(a3), "r"(b0), "r"(b1))

#define MMAH8(c0, c1, a0, a1, b0) asm volatile( \
    "mma.sync.aligned.m16n8k8.row.col.f16.f16.f16.f16 " \
    "{%0,%1}, {%2,%3}, {%4}, {%0,%1};" \
    : "+r"(c0), "+r"(c1) : "r"(a0), "r"(a1), "r"(b0))

__device__ __forceinline__ uint32_t smem_u32(const void* p) {
    uint32_t a;
    asm("{ .reg .u64 t; cvta.to.shared.u64 t, %1; cvt.u32.u64 %0, t; }" : "=r"(a) : "l"(p));
    return a;
}
__device__ __forceinline__ uint32_t lds32(uint32_t a) {
    uint32_t v; asm volatile("ld.shared.b32 %0, [%1];" : "=r"(v) : "r"(a)); return v;
}
__device__ __forceinline__ uint2 lds64(uint32_t a) {
    uint2 v; asm volatile("ld.shared.v2.b32 {%0,%1}, [%2];" : "=r"(v.x), "=r"(v.y) : "r"(a)); return v;
}
__device__ __forceinline__ uint4 lds128(uint32_t a) {
    uint4 v;
    asm volatile("ld.shared.v4.b32 {%0,%1,%2,%3}, [%4];"
                 : "=r"(v.x), "=r"(v.y), "=r"(v.z), "=r"(v.w) : "r"(a));
    return v;
}
__device__ __forceinline__ uint32_t packh(float a, float b) {
    __half2 h = __floats2half2_rn(a, b);
    return *(uint32_t*)&h;
}
// bias-add + gelu(tanh) on packed f16x2
__device__ __forceinline__ uint32_t gb(uint32_t cu, uint32_t bu) {
    __half2 x = __hadd2(*(__half2*)&cu, *(__half2*)&bu);
    const __half2 c0 = __float2half2_rn(0.7978845608f);
    const __half2 c1 = __float2half2_rn(0.03567740814f);
    __half2 u = __hmul2(x, x);
    __half2 z = __hmul2(x, __hfma2(u, c1, c0));
    uint32_t zi = *(uint32_t*)&z, ti;
    asm("tanh.approx.f16x2 %0, %1;" : "=r"(ti) : "r"(zi));
    __half2 t = *(__half2*)&ti;
    __half2 hh = __hmul2(x, __float2half2_rn(0.5f));
    __half2 g = __hfma2(hh, t, hh);
    return *(uint32_t*)&g;
}

__global__ void __launch_bounds__(TB, 3)
mhd_wl4(const float* __restrict__ flow, const float* __restrict__ Bf,
        const float* __restrict__ W1, const float* __restrict__ b1,
        const float* __restrict__ W2, const float* __restrict__ b2,
        const float* __restrict__ W3, const float* __restrict__ b3,
        const float* __restrict__ W4, const float* __restrict__ b4,
        float* __restrict__ out)
{
    extern __shared__ char smc[];
    const int tid  = threadIdx.x;
    const int wid  = tid >> 5;
    const int lane = tid & 31;
    const int q    = lane & 3;
    const int rsub = lane >> 2;
    const uint32_t smb = smem_u32(smc);

    // ---------------- stage weight B-fragment tables (once per CTA) ----------------
    for (int e = tid; e < 2048; e += TB) {      // W2T
        int l = e & 31, tp = (e >> 5) & 7, sx = e >> 8;
        int n0 = (2 * tp) * 8 + (l >> 2), n1 = n0 + 8;
        int k0 = sx * 16 + (l & 3) * 2;
        uint4 v;
        v.x = packh(W2[k0 * 128 + n0],       W2[(k0 + 1) * 128 + n0]);
        v.y = packh(W2[(k0 + 8) * 128 + n0], W2[(k0 + 9) * 128 + n0]);
        v.z = packh(W2[k0 * 128 + n1],       W2[(k0 + 1) * 128 + n1]);
        v.w = packh(W2[(k0 + 8) * 128 + n1], W2[(k0 + 9) * 128 + n1]);
        *(uint4*)(smc + O_W2T + e * 16) = v;
    }
    for (int e = tid; e < 1024; e += TB) {      // W3T
        int l = e & 31, tp = (e >> 5) & 3, sx = e >> 7;
        int n0 = (2 * tp) * 8 + (l >> 2), n1 = n0 + 8;
        int k0 = sx * 16 + (l & 3) * 2;
        uint4 v;
        v.x = packh(W3[k0 * 64 + n0],       W3[(k0 + 1) * 64 + n0]);
        v.y = packh(W3[(k0 + 8) * 64 + n0], W3[(k0 + 9) * 64 + n0]);
        v.z = packh(W3[k0 * 64 + n1],       W3[(k0 + 1) * 64 + n1]);
        v.w = packh(W3[(k0 + 8) * 64 + n1], W3[(k0 + 9) * 64 + n1]);
        *(uint4*)(smc + O_W3T + e * 16) = v;
    }
    for (int e = tid; e < 256; e += TB) {       // W1T (k>=6 zero)
        int l = e & 31, tp = e >> 5;
        int n0 = (2 * tp) * 8 + (l >> 2), n1 = n0 + 8;
        int k0 = (l & 3) * 2;
        float a0 = (k0 < 6) ? W1[k0 * 128 + n0] : 0.f;
        float a1 = (k0 + 1 < 6) ? W1[(k0 + 1) * 128 + n0] : 0.f;
        float a2 = (k0 < 6) ? W1[k0 * 128 + n1] : 0.f;
        float a3 = (k0 + 1 < 6) ? W1[(k0 + 1) * 128 + n1] : 0.f;
        uint2 v; v.x = packh(a0, a1); v.y = packh(a2, a3);
        *(uint2*)(smc + O_W1T + e * 8) = v;
    }
    for (int i = tid; i < 64; i += TB)
        *(uint32_t*)(smc + O_B1H + i * 4) = packh(b1[(i >> 2) * 8 + (i & 3) * 2],
                                                  b1[(i >> 2) * 8 + (i & 3) * 2 + 1]);
    for (int i = tid; i < 64; i += TB)
        *(uint32_t*)(smc + O_B2H + i * 4) = packh(b2[(i >> 2) * 8 + (i & 3) * 2],
                                                  b2[(i >> 2) * 8 + (i & 3) * 2 + 1]);
    for (int i = tid; i < 32; i += TB)
        *(uint32_t*)(smc + O_B3H + i * 4) = packh(b3[(i >> 2) * 8 + (i & 3) * 2],
                                                  b3[(i >> 2) * 8 + (i & 3) * 2 + 1]);
    for (int i = tid; i < 96; i += TB) {        // W4H[c*32+p] = {W4[2p][c], W4[2p+1][c]}
        int c = i >> 5, p = i & 31;
        *(uint32_t*)(smc + O_W4H + i * 4) = packh(W4[2 * p * 3 + c], W4[(2 * p + 1) * 3 + c]);
    }
    if (tid < 3) ((float*)(smc + O_B4))[tid] = b4[tid];
    __syncthreads();   // only block barrier in the kernel

    // Balanced persistent loop: all 444 CTAs resident; tiles strided by GRID.
    for (int tile = blockIdx.x; tile < NTILES; tile += GRID) {
        const int vbase = tile * 128 + wid * 16;   // warp's 16-voxel strip
        const int b  = vbase >> 18;
        const int sb = vbase & (SP - 1);
        const float* Fb = flow + b * 3 * SP;
        const float* Bx = Bf + b * 3 * SP;
        const float* By = Bx + SP;
        const float* Bz = Bx + 2 * SP;

        // ---------------- P0: features into A-frags; lorentz -> smem stash ----
        const int s0 = sb + rsub, s1 = s0 + 8;
        uint32_t fa0, fa1;
        {
            float l0, h0, l1, h1;
            if (q == 0)      { l0 = Fb[s0]; h0 = Fb[SP + s0]; l1 = Fb[s1]; h1 = Fb[SP + s1]; }
            else if (q == 1) { l0 = Fb[2 * SP + s0]; h0 = Bx[s0]; l1 = Fb[2 * SP + s1]; h1 = Bx[s1]; }
            else if (q == 2) { l0 = By[s0]; h0 = Bz[s0]; l1 = By[s1]; h1 = Bz[s1]; }
            else             { l0 = h0 = l1 = h1 = 0.f; }
            fa0 = packh(l0, h0);
            fa1 = packh(l1, h1);
        }
        __syncwarp();          // prev tile's L4 reads of LZ rows complete
        if (lane < 16) {
            const int sm = sb + lane;
            const int h = sm >> 12, w = (sm >> 6) & 63, d = sm & 63;
            const int H = h << 12, Wo = w << 6;
            const int hp = ((h + 1) & 63) << 12, hm = ((h - 1) & 63) << 12;
            const int wp = ((w + 1) & 63) << 6,  wm2 = ((w - 1) & 63) << 6;
            const int dp = (d + 1) & 63, dm = (d - 1) & 63;
            const float bx = Bx[H + Wo + d], by = By[H + Wo + d], bz = Bz[H + Wo + d];
            const float Jx = 0.5f * ((Bz[H + wp + d] - Bz[H + wm2 + d]) - (By[H + Wo + dp] - By[H + Wo + dm]));
            const float Jy = 0.5f * ((Bx[H + Wo + dp] - Bx[H + Wo + dm]) - (Bz[hp + Wo + d] - Bz[hm + Wo + d]));
            const float Jz = 0.5f * ((By[hp + Wo + d] - By[hm + Wo + d]) - (Bx[H + wp + d] - Bx[H + wm2 + d]));
            float* lz = (float*)(smc + O_LZ) + (wid * 16 + lane) * 3;
            lz[0] = (Jy * bz - Jz * by) * 2500.0f;
            lz[1] = (Jz * bx - Jx * bz) * 2500.0f;
            lz[2] = (Jx * by - Jy * bx) * 2500.0f;
        }

        uint32_t a[16][2];    // activations (A-frags / gelu'd C-frags)
        uint32_t c[16][2];    // accumulators

        // ---------------- L1: 6(->8) -> 128, k8 MMA ----------------
        #pragma unroll
        for (int t = 0; t < 16; t++) { c[t][0] = 0u; c[t][1] = 0u; }
        #pragma unroll
        for (int tp = 0; tp < 8; tp++) {
            uint2 B1f = lds64(smb + O_W1T + (uint32_t)(tp * 32 + lane) * 8);
            MMAH8(c[2 * tp][0], c[2 * tp][1], fa0, fa1, B1f.x);
            MMAH8(c[2 * tp + 1][0], c[2 * tp + 1][1], fa0, fa1, B1f.y);
        }
        #pragma unroll
        for (int t = 0; t < 16; t++) {
            uint32_t bb = lds32(smb + O_B1H + (uint32_t)(t * 4 + q) * 4);
            a[t][0] = gb(c[t][0], bb);
            a[t][1] = gb(c[t][1], bb);
        }

        // ---------------- L2: 128 -> 128 ----------------
        #pragma unroll
        for (int t = 0; t < 16; t++) { c[t][0] = 0u; c[t][1] = 0u; }
        #pragma unroll
        for (int sx = 0; sx < 8; sx++) {
            const uint32_t a0 = a[2 * sx][0], a1 = a[2 * sx][1];
            const uint32_t a2 = a[2 * sx + 1][0], a3 = a[2 * sx + 1][1];
            #pragma unroll
            for (int tp = 0; tp < 8; tp++) {
                uint4 Bf2 = lds128(smb + O_W2T + (uint32_t)((sx * 8 + tp) * 32 + lane) * 16);
                MMAH16(c[2 * tp][0], c[2 * tp][1], a0, a1, a2, a3, Bf2.x, Bf2.y);
                MMAH16(c[2 * tp + 1][0], c[2 * tp + 1][1], a0, a1, a2, a3, Bf2.z, Bf2.w);
            }
        }
        #pragma unroll
        for (int t = 0; t < 16; t++) {
            uint32_t bb = lds32(smb + O_B2H + (uint32_t)(t * 4 + q) * 4);
            a[t][0] = gb(c[t][0], bb);
            a[t][1] = gb(c[t][1], bb);
        }

        // ---------------- L3: 128 -> 64 ----------------
        uint32_t c3[8][2];
        #pragma unroll
        for (int t = 0; t < 8; t++) { c3[t][0] = 0u; c3[t][1] = 0u; }
        #pragma unroll
        for (int sx = 0; sx < 8; sx++) {
            const uint32_t a0 = a[2 * sx][0], a1 = a[2 * sx][1];
            const uint32_t a2 = a[2 * sx + 1][0], a3 = a[2 * sx + 1][1];
            #pragma unroll
            for (int tp = 0; tp < 4; tp++) {
                uint4 Bf3 = lds128(smb + O_W3T + (uint32_t)((sx * 4 + tp) * 32 + lane) * 16);
                MMAH16(c3[2 * tp][0], c3[2 * tp][1], a0, a1, a2, a3, Bf3.x, Bf3.y);
                MMAH16(c3[2 * tp + 1][0], c3[2 * tp + 1][1], a0, a1, a2, a3, Bf3.z, Bf3.w);
            }
        }
        #pragma unroll
        for (int t = 0; t < 8; t++) {
            uint32_t bb = lds32(smb + O_B3H + (uint32_t)(t * 4 + q) * 4);
            c3[t][0] = gb(c3[t][0], bb);    // x3 in place
            c3[t][1] = gb(c3[t][1], bb);
        }

        // ---------------- L4: 64 -> 3 (hfma2 dot + quad butterfly) ----------------
        __half2 acc[2][3];
        #pragma unroll
        for (int r = 0; r < 2; r++)
            #pragma unroll
            for (int cc = 0; cc < 3; cc++) acc[r][cc] = __float2half2_rn(0.f);
        #pragma unroll
        for (int t = 0; t < 8; t++) {
            #pragma unroll
            for (int cc = 0; cc < 3; cc++) {
                uint32_t wu = lds32(smb + O_W4H + (uint32_t)(cc * 32 + t * 4 + q) * 4);
                __half2 wh = *(__half2*)&wu;
                acc[0][cc] = __hfma2(*(__half2*)&c3[t][0], wh, acc[0][cc]);
                acc[1][cc] = __hfma2(*(__half2*)&c3[t][1], wh, acc[1][cc]);
            }
        }
        float pe[2][3];
        #pragma unroll
        for (int r = 0; r < 2; r++)
            #pragma unroll
            for (int cc = 0; cc < 3; cc++) {
                float2 f = __half22float2(acc[r][cc]);
                float vv = f.x + f.y;
                vv += __shfl_xor_sync(0xffffffffu, vv, 1);
                vv += __shfl_xor_sync(0xffffffffu, vv, 2);
                pe[r][cc] = vv + ((const float*)(smc + O_B4))[cc];
            }
        __syncwarp();          // LZ stores (lanes 0-15) visible to all lanes
        if (q < 3) {
            const float L0 = ((const float*)(smc + O_LZ))[(wid * 16 + rsub) * 3 + q];
            const float L1 = ((const float*)(smc + O_LZ))[(wid * 16 + rsub + 8) * 3 + q];
            float* ob = out + b * 3 * SP + q * SP;
            ob[s0] = L0 + 0.1f * pe[0][q];
            ob[s1] = L1 + 0.1f * pe[1][q];
        }
    }
}

extern "C" void kernel_launch(void* const* d_in, const int* in_sizes, int n_in,
                              void* d_out, int out_size)
{
    (void)in_sizes; (void)n_in; (void)out_size;
    cudaFuncSetAttribute(mhd_wl4, cudaFuncAttributeMaxDynamicSharedMemorySize, SMEM_BYTES);
    mhd_wl4<<<GRID, TB, SMEM_BYTES>>>(
        (const float*)d_in[0], (const float*)d_in[1], (const float*)d_in[2],
        (const float*)d_in[3], (const float*)d_in[4], (const float*)d_in[5],
        (const float*)d_in[6], (const float*)d_in[7], (const float*)d_in[8],
        (const float*)d_in[9], (float*)d_out);
}